// round 3
// baseline (speedup 1.0000x reference)
#include <cuda_runtime.h>
#include <cstdint>

// ---------------------------------------------------------------------------
// Problem constants
// ---------------------------------------------------------------------------
#define kN 100000
#define kE 1600000
#define kIN 128
#define kOUT 64
#define kEDGE 32
#define NEG_SLOPE 0.2f
#define SCAN_BLOCKS 98   // ceil(100000/1024)

// ---------------------------------------------------------------------------
// Device scratch (static globals; no runtime allocation)
// ---------------------------------------------------------------------------
__device__ __align__(16) float g_feat_src[kN * kOUT];       // 25.6 MB
__device__ __align__(16) float g_feat_dst[kN * kOUT];       // 25.6 MB
__device__ __align__(16) float g_eedge[kE * kOUT];          // 409.6 MB
__device__ __align__(16) float g_logits[kE * 4];            // 25.6 MB
__device__ __align__(16) float g_WcT[kIN * kIN];            // combined [k][j] (j<64: W_src, else W_dst)
__device__ __align__(16) float g_WeT[kEDGE * kOUT];         // [k][j]
__device__ int   g_deg[kN];
__device__ int   g_cursor[kN];
__device__ int   g_rowptr[kN + 1];
__device__ int   g_edge_list[kE];
__device__ int   g_partial[SCAN_BLOCKS];

// ---------------------------------------------------------------------------
// Packed f32x2 FMA helpers (sm_103a FFMA2 — 2x fp32 FMA throughput)
// ---------------------------------------------------------------------------
__device__ __forceinline__ void ffma2(uint64_t& d, uint64_t a, uint64_t b) {
    asm("fma.rn.f32x2 %0, %1, %2, %0;" : "+l"(d) : "l"(a), "l"(b));
}
__device__ __forceinline__ uint64_t pack2(float x, float y) {
    uint64_t r; asm("mov.b64 %0, {%1, %2};" : "=l"(r) : "f"(x), "f"(y)); return r;
}
__device__ __forceinline__ void unpack2(uint64_t v, float& x, float& y) {
    asm("mov.b64 {%0, %1}, %2;" : "=f"(x), "=f"(y) : "l"(v));
}

// ---------------------------------------------------------------------------
// K0: transpose weights once (tiny)
// ---------------------------------------------------------------------------
__global__ void prep_weights_kernel(const float* __restrict__ Ws,
                                    const float* __restrict__ Wd,
                                    const float* __restrict__ We) {
    int stride = gridDim.x * blockDim.x;
    int t0 = blockIdx.x * blockDim.x + threadIdx.x;
    for (int i = t0; i < kIN * kIN; i += stride) {
        int k = i >> 7, j = i & 127;
        g_WcT[i] = (j < 64) ? Ws[j * kIN + k] : Wd[(j - 64) * kIN + k];
    }
    for (int i = t0; i < kEDGE * kOUT; i += stride) {
        int k = i >> 6, j = i & 63;
        g_WeT[i] = We[j * kEDGE + k];
    }
}

__global__ void zero_kernel() {
    int i = blockIdx.x * blockDim.x + threadIdx.x;
    if (i < kN) { g_deg[i] = 0; g_cursor[i] = 0; }
}

// ---------------------------------------------------------------------------
// K1: node projections  feat_src/feat_dst[N,64] = node_feat @ {W_src,W_dst}^T
// Tile: 64 nodes x 128 outs per block (256 threads, each 8 nodes x 4 outs)
// ---------------------------------------------------------------------------
__global__ void proj_kernel(const float* __restrict__ node_feat) {
    __shared__ float sAt[kIN][65];   // A^T tile, pad 65 -> conflict-free
    int tid = threadIdx.x;
    int n0 = blockIdx.x * 64;

#pragma unroll
    for (int r = 0; r < 32; r++) {
        int idx = r * 256 + tid;          // 0..8191
        int node = idx >> 7;
        int k = idx & 127;
        int gn = n0 + node;
        float v = (gn < kN) ? node_feat[gn * kIN + k] : 0.f;
        sAt[k][node] = v;
    }
    __syncthreads();

    int tx = tid & 31;   // outs j = tx*4 .. tx*4+3   (0..127)
    int ty = tid >> 5;   // nodes ty*8 .. ty*8+7
    uint64_t acc[8][2];
#pragma unroll
    for (int i = 0; i < 8; i++) { acc[i][0] = 0ull; acc[i][1] = 0ull; }

    const float4* Wp = reinterpret_cast<const float4*>(g_WcT) + tx;
#pragma unroll 4
    for (int k = 0; k < kIN; k++) {
        float4 w = __ldg(Wp + k * 32);
        uint64_t w01 = pack2(w.x, w.y), w23 = pack2(w.z, w.w);
#pragma unroll
        for (int i = 0; i < 8; i++) {
            float a = sAt[k][ty * 8 + i];
            uint64_t aa = pack2(a, a);
            ffma2(acc[i][0], aa, w01);
            ffma2(acc[i][1], aa, w23);
        }
    }

    int j = tx * 4;
#pragma unroll
    for (int i = 0; i < 8; i++) {
        int gn = n0 + ty * 8 + i;
        if (gn >= kN) continue;
        float4 o;
        unpack2(acc[i][0], o.x, o.y);
        unpack2(acc[i][1], o.z, o.w);
        if (j < 64) *reinterpret_cast<float4*>(&g_feat_src[gn * 64 + j]) = o;
        else        *reinterpret_cast<float4*>(&g_feat_dst[gn * 64 + (j - 64)]) = o;
    }
}

// ---------------------------------------------------------------------------
// K2: edge GEMM  e_edge[E,64] = edge_feat[E,32] @ W_edge^T
// Tile: 128 edges x 64 outs per block (256 threads, each 8 edges x 4 outs)
// ---------------------------------------------------------------------------
__global__ void edge_gemm_kernel(const float* __restrict__ edge_feat) {
    __shared__ float sAt[kEDGE][133];
    int tid = threadIdx.x;
    int e0 = blockIdx.x * 128;

#pragma unroll
    for (int r = 0; r < 16; r++) {
        int idx = r * 256 + tid;          // 0..4095
        int el = idx >> 5;
        int k = idx & 31;
        sAt[k][el] = edge_feat[(size_t)(e0 + el) * kEDGE + k];
    }
    __syncthreads();

    int tx = tid & 15;   // outs j = tx*4
    int ty = tid >> 4;   // edges ty*8 .. +7
    uint64_t acc[8][2];
#pragma unroll
    for (int i = 0; i < 8; i++) { acc[i][0] = 0ull; acc[i][1] = 0ull; }

    const float4* Wp = reinterpret_cast<const float4*>(g_WeT) + tx;
#pragma unroll
    for (int k = 0; k < kEDGE; k++) {
        float4 w = __ldg(Wp + k * 16);
        uint64_t w01 = pack2(w.x, w.y), w23 = pack2(w.z, w.w);
#pragma unroll
        for (int i = 0; i < 8; i++) {
            float a = sAt[k][ty * 8 + i];
            uint64_t aa = pack2(a, a);
            ffma2(acc[i][0], aa, w01);
            ffma2(acc[i][1], aa, w23);
        }
    }

    int j = tx * 4;
#pragma unroll
    for (int i = 0; i < 8; i++) {
        int e = e0 + ty * 8 + i;
        float4 o;
        unpack2(acc[i][0], o.x, o.y);
        unpack2(acc[i][1], o.z, o.w);
        *reinterpret_cast<float4*>(&g_eedge[(size_t)e * 64 + j]) = o;
    }
}

// ---------------------------------------------------------------------------
// K3: edge logits + dst-degree histogram.  One warp per edge.
// ---------------------------------------------------------------------------
__global__ void edge_logits_kernel(const int* __restrict__ src,
                                   const int* __restrict__ dst,
                                   const float* __restrict__ attn) {
    int e = (blockIdx.x * blockDim.x + threadIdx.x) >> 5;   // grid = exactly E warps
    int lane = threadIdx.x & 31;

    int s = __ldg(&src[e]);
    int d = __ldg(&dst[e]);

    float fs0 = g_feat_src[s * 64 + lane];
    float fs1 = g_feat_src[s * 64 + 32 + lane];
    float fd0 = g_feat_dst[d * 64 + lane];
    float fd1 = g_feat_dst[d * 64 + 32 + lane];
    size_t eb = (size_t)e * 64;
    float ee0 = g_eedge[eb + lane];
    float ee1 = g_eedge[eb + 32 + lane];

    float x0 = fs0 + fd0 + ee0; x0 = (x0 > 0.f) ? x0 : NEG_SLOPE * x0;
    float x1 = fs1 + fd1 + ee1; x1 = (x1 > 0.f) ? x1 : NEG_SLOPE * x1;

    // attn flat layout [h*16+hd] == feature index
    float p0 = x0 * __ldg(&attn[lane]);
    float p1 = x1 * __ldg(&attn[32 + lane]);

#pragma unroll
    for (int o = 8; o > 0; o >>= 1) {
        p0 += __shfl_xor_sync(0xffffffffu, p0, o);
        p1 += __shfl_xor_sync(0xffffffffu, p1, o);
    }
    // lane0: head0 (p0), head2 (p1); lane16: head1 (p0), head3 (p1)
    float q0 = __shfl_sync(0xffffffffu, p0, 16);
    float q1 = __shfl_sync(0xffffffffu, p1, 16);
    if (lane == 0) {
        reinterpret_cast<float4*>(g_logits)[e] = make_float4(p0, q0, p1, q1);
        atomicAdd(&g_deg[d], 1);
    }
}

// ---------------------------------------------------------------------------
// Scan: deg -> rowptr (exclusive)
// ---------------------------------------------------------------------------
__global__ void scanA_kernel() {
    __shared__ int warpsums[32];
    int i = blockIdx.x * 1024 + threadIdx.x;
    int v = (i < kN) ? g_deg[i] : 0;
    int lane = threadIdx.x & 31, wid = threadIdx.x >> 5;
    int x = v;
#pragma unroll
    for (int o = 1; o < 32; o <<= 1) {
        int t = __shfl_up_sync(0xffffffffu, x, o);
        if (lane >= o) x += t;
    }
    if (lane == 31) warpsums[wid] = x;
    __syncthreads();
    if (wid == 0) {
        int s = warpsums[lane];
#pragma unroll
        for (int o = 1; o < 32; o <<= 1) {
            int t = __shfl_up_sync(0xffffffffu, s, o);
            if (lane >= o) s += t;
        }
        warpsums[lane] = s;
    }
    __syncthreads();
    int base = wid ? warpsums[wid - 1] : 0;
    int incl = base + x;
    if (i < kN) g_rowptr[i] = incl - v;       // exclusive (block-local)
    if (threadIdx.x == 1023) g_partial[blockIdx.x] = incl;
}

__global__ void scanB_kernel() {
    if (threadIdx.x == 0) {
        int s = 0;
        for (int b = 0; b < SCAN_BLOCKS; b++) { int t = g_partial[b]; g_partial[b] = s; s += t; }
    }
}

__global__ void scanC_kernel() {
    int i = blockIdx.x * 1024 + threadIdx.x;
    if (i < kN) g_rowptr[i] += g_partial[blockIdx.x];
    if (blockIdx.x == 0 && threadIdx.x == 0) g_rowptr[kN] = kE;
}

// ---------------------------------------------------------------------------
// K4: scatter edge ids into CSR buckets
// ---------------------------------------------------------------------------
__global__ void scatter_kernel(const int* __restrict__ dst) {
    int e = blockIdx.x * blockDim.x + threadIdx.x;
    int d = dst[e];
    int p = atomicAdd(&g_cursor[d], 1);
    g_edge_list[g_rowptr[d] + p] = e;
}

// ---------------------------------------------------------------------------
// K5: per-dst softmax + weighted aggregation. One warp per node, atomic-free.
// ---------------------------------------------------------------------------
__global__ void aggregate_kernel(const int* __restrict__ src,
                                 const float* __restrict__ bias,
                                 float* __restrict__ rst,
                                 float* __restrict__ alpha_out,
                                 int write_alpha) {
    int n = (blockIdx.x * blockDim.x + threadIdx.x) >> 5;  // grid = exactly N warps
    int lane = threadIdx.x & 31;
    int beg = g_rowptr[n], end = g_rowptr[n + 1];
    const float4* lg4 = reinterpret_cast<const float4*>(g_logits);

    // ---- per-head max ----
    float m0 = -3e38f, m1 = -3e38f, m2 = -3e38f, m3 = -3e38f;
    for (int i = beg + lane; i < end; i += 32) {
        float4 l = lg4[g_edge_list[i]];
        m0 = fmaxf(m0, l.x); m1 = fmaxf(m1, l.y);
        m2 = fmaxf(m2, l.z); m3 = fmaxf(m3, l.w);
    }
#pragma unroll
    for (int o = 16; o > 0; o >>= 1) {
        m0 = fmaxf(m0, __shfl_xor_sync(0xffffffffu, m0, o));
        m1 = fmaxf(m1, __shfl_xor_sync(0xffffffffu, m1, o));
        m2 = fmaxf(m2, __shfl_xor_sync(0xffffffffu, m2, o));
        m3 = fmaxf(m3, __shfl_xor_sync(0xffffffffu, m3, o));
    }

    // ---- per-head exp-sum ----
    float s0 = 0.f, s1 = 0.f, s2 = 0.f, s3 = 0.f;
    for (int i = beg + lane; i < end; i += 32) {
        float4 l = lg4[g_edge_list[i]];
        s0 += __expf(l.x - m0); s1 += __expf(l.y - m1);
        s2 += __expf(l.z - m2); s3 += __expf(l.w - m3);
    }
#pragma unroll
    for (int o = 16; o > 0; o >>= 1) {
        s0 += __shfl_xor_sync(0xffffffffu, s0, o);
        s1 += __shfl_xor_sync(0xffffffffu, s1, o);
        s2 += __shfl_xor_sync(0xffffffffu, s2, o);
        s3 += __shfl_xor_sync(0xffffffffu, s3, o);
    }
    float r0 = (s0 > 0.f) ? 1.f / s0 : 0.f;
    float r1 = (s1 > 0.f) ? 1.f / s1 : 0.f;
    float r2 = (s2 > 0.f) ? 1.f / s2 : 0.f;
    float r3 = (s3 > 0.f) ? 1.f / s3 : 0.f;

    // ---- alpha output (lane-parallel over edges) ----
    if (write_alpha) {
        float4* a4 = reinterpret_cast<float4*>(alpha_out);
        for (int i = beg + lane; i < end; i += 32) {
            int e = g_edge_list[i];
            float4 l = lg4[e];
            a4[e] = make_float4(__expf(l.x - m0) * r0, __expf(l.y - m1) * r1,
                                __expf(l.z - m2) * r2, __expf(l.w - m3) * r3);
        }
    }

    // ---- weighted message aggregation (edge-serial, feature-parallel) ----
    float acc0 = 0.f, acc1 = 0.f;
    bool lo = lane < 16;   // head of feature `lane` is 0/1; of `lane+32` is 2/3
    for (int i = beg; i < end; i++) {
        int e = g_edge_list[i];
        int sn = __ldg(&src[e]);
        float4 l = lg4[e];
        float a0 = __expf(l.x - m0) * r0, a1 = __expf(l.y - m1) * r1;
        float a2 = __expf(l.z - m2) * r2, a3 = __expf(l.w - m3) * r3;
        float al0 = lo ? a0 : a1;
        float al1 = lo ? a2 : a3;
        acc0 += al0 * g_feat_src[sn * 64 + lane];
        acc1 += al1 * g_feat_src[sn * 64 + 32 + lane];
    }
    rst[n * 64 + lane]      = acc0 + __ldg(&bias[lane]);
    rst[n * 64 + 32 + lane] = acc1 + __ldg(&bias[32 + lane]);
}

// ---------------------------------------------------------------------------
// Launcher
// ---------------------------------------------------------------------------
extern "C" void kernel_launch(void* const* d_in, const int* in_sizes, int n_in,
                              void* d_out, int out_size) {
    (void)in_sizes; (void)n_in;
    const float* node_feat = (const float*)d_in[0];
    const float* edge_feat = (const float*)d_in[1];
    const float* W_src     = (const float*)d_in[2];
    const float* W_dst     = (const float*)d_in[3];
    const float* W_edge    = (const float*)d_in[4];
    const float* attn      = (const float*)d_in[5];
    const float* bias      = (const float*)d_in[6];
    const int*   src       = (const int*)d_in[7];
    const int*   dst       = (const int*)d_in[8];

    float* out = (float*)d_out;
    int write_alpha = (out_size >= kN * kOUT + kE * 4) ? 1 : 0;
    float* alpha_out = out + (size_t)kN * kOUT;

    prep_weights_kernel<<<64, 256>>>(W_src, W_dst, W_edge);
    zero_kernel<<<(kN + 255) / 256, 256>>>();
    proj_kernel<<<(kN + 63) / 64, 256>>>(node_feat);
    edge_gemm_kernel<<<kE / 128, 256>>>(edge_feat);
    edge_logits_kernel<<<kE / 8, 256>>>(src, dst, attn);
    scanA_kernel<<<SCAN_BLOCKS, 1024>>>();
    scanB_kernel<<<1, 32>>>();
    scanC_kernel<<<SCAN_BLOCKS, 1024>>>();
    scatter_kernel<<<kE / 256, 256>>>(dst);
    aggregate_kernel<<<kN / 8, 256>>>(src, bias, out, alpha_out, write_alpha);
}

// round 5
// speedup vs baseline: 1.3668x; 1.3668x over previous
#include <cuda_runtime.h>
#include <cstdint>

// ---------------------------------------------------------------------------
// Problem constants
// ---------------------------------------------------------------------------
#define kN 100000
#define kE 1600000
#define kIN 128
#define kOUT 64
#define kEDGE 32
#define NEG_SLOPE 0.2f
#define SCAN_BLOCKS 98   // ceil(100000/1024)

// ---------------------------------------------------------------------------
// Device scratch (static globals; no runtime allocation)
// ---------------------------------------------------------------------------
__device__ __align__(16) float g_feat_src[kN * kOUT];       // 25.6 MB
__device__ __align__(16) float g_feat_dst[kN * kOUT];       // 25.6 MB
__device__ __align__(16) float g_logits[kE * 4];            // 25.6 MB
__device__ __align__(16) float g_alpha[kE * 4];             // 25.6 MB scratch
__device__ __align__(16) float g_WcT[kIN * kIN];            // [k][j] (j<64: W_src, else W_dst)
__device__ __align__(16) float g_WeT[kEDGE * kOUT];         // [k][j]
__device__ int   g_deg[kN];
__device__ int   g_cursor[kN];
__device__ int   g_rowptr[kN + 1];
__device__ int   g_edge_list[kE];
__device__ int   g_partial[SCAN_BLOCKS];

// ---------------------------------------------------------------------------
// Packed f32x2 FMA helpers (sm_103a FFMA2 — 2x fp32 FMA throughput)
// ---------------------------------------------------------------------------
__device__ __forceinline__ void ffma2(uint64_t& d, uint64_t a, uint64_t b) {
    asm("fma.rn.f32x2 %0, %1, %2, %0;" : "+l"(d) : "l"(a), "l"(b));
}
__device__ __forceinline__ uint64_t pack2(float x, float y) {
    uint64_t r; asm("mov.b64 %0, {%1, %2};" : "=l"(r) : "f"(x), "f"(y)); return r;
}
__device__ __forceinline__ void unpack2(uint64_t v, float& x, float& y) {
    asm("mov.b64 {%0, %1}, %2;" : "=f"(x), "=f"(y) : "l"(v));
}

// ---------------------------------------------------------------------------
// K0: transpose weights once (tiny)
// ---------------------------------------------------------------------------
__global__ void prep_weights_kernel(const float* __restrict__ Ws,
                                    const float* __restrict__ Wd,
                                    const float* __restrict__ We) {
    int stride = gridDim.x * blockDim.x;
    int t0 = blockIdx.x * blockDim.x + threadIdx.x;
    for (int i = t0; i < kIN * kIN; i += stride) {
        int k = i >> 7, j = i & 127;
        g_WcT[i] = (j < 64) ? Ws[j * kIN + k] : Wd[(j - 64) * kIN + k];
    }
    for (int i = t0; i < kEDGE * kOUT; i += stride) {
        int k = i >> 6, j = i & 63;
        g_WeT[i] = We[j * kEDGE + k];
    }
}

__global__ void zero_kernel() {
    int i = blockIdx.x * blockDim.x + threadIdx.x;
    if (i < kN) { g_deg[i] = 0; g_cursor[i] = 0; }
}

// ---------------------------------------------------------------------------
// K1: node projections  feat_src/feat_dst[N,64] = node_feat @ {W_src,W_dst}^T
// Tile: 64 nodes x 128 outs per block (256 threads, each 8 nodes x 4 outs)
// Vectorized smem A-loads (float4) to keep L1 pressure off the fma pipe.
// ---------------------------------------------------------------------------
__global__ void proj_kernel(const float* __restrict__ node_feat) {
    __shared__ __align__(16) float sAt[kIN][68];   // pad 68: 16B-aligned rows
    int tid = threadIdx.x;
    int n0 = blockIdx.x * 64;

#pragma unroll
    for (int r = 0; r < 32; r++) {
        int idx = r * 256 + tid;          // 0..8191
        int node = idx >> 7;
        int k = idx & 127;
        int gn = n0 + node;
        float v = (gn < kN) ? node_feat[gn * kIN + k] : 0.f;
        sAt[k][node] = v;
    }
    __syncthreads();

    int tx = tid & 31;   // outs j = tx*4 .. tx*4+3   (0..127)
    int ty = tid >> 5;   // nodes ty*8 .. ty*8+7
    uint64_t acc[8][2];
#pragma unroll
    for (int i = 0; i < 8; i++) { acc[i][0] = 0ull; acc[i][1] = 0ull; }

    const float4* Wp = reinterpret_cast<const float4*>(g_WcT) + tx;
#pragma unroll 8
    for (int k = 0; k < kIN; k++) {
        float4 w = __ldg(Wp + k * 32);
        uint64_t w01 = pack2(w.x, w.y), w23 = pack2(w.z, w.w);
        float4 aA = *reinterpret_cast<const float4*>(&sAt[k][ty * 8]);
        float4 aB = *reinterpret_cast<const float4*>(&sAt[k][ty * 8 + 4]);
        { uint64_t aa = pack2(aA.x, aA.x); ffma2(acc[0][0], aa, w01); ffma2(acc[0][1], aa, w23); }
        { uint64_t aa = pack2(aA.y, aA.y); ffma2(acc[1][0], aa, w01); ffma2(acc[1][1], aa, w23); }
        { uint64_t aa = pack2(aA.z, aA.z); ffma2(acc[2][0], aa, w01); ffma2(acc[2][1], aa, w23); }
        { uint64_t aa = pack2(aA.w, aA.w); ffma2(acc[3][0], aa, w01); ffma2(acc[3][1], aa, w23); }
        { uint64_t aa = pack2(aB.x, aB.x); ffma2(acc[4][0], aa, w01); ffma2(acc[4][1], aa, w23); }
        { uint64_t aa = pack2(aB.y, aB.y); ffma2(acc[5][0], aa, w01); ffma2(acc[5][1], aa, w23); }
        { uint64_t aa = pack2(aB.z, aB.z); ffma2(acc[6][0], aa, w01); ffma2(acc[6][1], aa, w23); }
        { uint64_t aa = pack2(aB.w, aB.w); ffma2(acc[7][0], aa, w01); ffma2(acc[7][1], aa, w23); }
    }

    int j = tx * 4;
#pragma unroll
    for (int i = 0; i < 8; i++) {
        int gn = n0 + ty * 8 + i;
        if (gn >= kN) continue;
        float4 o;
        unpack2(acc[i][0], o.x, o.y);
        unpack2(acc[i][1], o.z, o.w);
        if (j < 64) *reinterpret_cast<float4*>(&g_feat_src[gn * 64 + j]) = o;
        else        *reinterpret_cast<float4*>(&g_feat_dst[gn * 64 + (j - 64)]) = o;
    }
}

// ---------------------------------------------------------------------------
// K2: FUSED edge GEMM + logits + degree histogram.
// e_edge never touches DRAM: GEMM accumulators stay in registers, epilogue
// gathers feat_src/feat_dst rows (L2-resident), applies leaky-relu + attn dot,
// reduces per-head within 4-lane groups, writes logits[E,4].
// Tile: 128 edges x 64 outs per block (256 threads: tx=outs/4, ty=edges/8)
// ---------------------------------------------------------------------------
__global__ void fused_edge_kernel(const float* __restrict__ edge_feat,
                                  const int* __restrict__ src,
                                  const int* __restrict__ dst,
                                  const float* __restrict__ attn) {
    __shared__ __align__(16) float sAt[kEDGE][132];   // pad 132: 16B-aligned rows
    int tid = threadIdx.x;
    int e0 = blockIdx.x * 128;

#pragma unroll
    for (int r = 0; r < 16; r++) {
        int idx = r * 256 + tid;          // 0..4095
        int el = idx >> 5;
        int k = idx & 31;
        sAt[k][el] = edge_feat[(size_t)(e0 + el) * kEDGE + k];
    }
    __syncthreads();

    int tx = tid & 15;   // outs j = tx*4 .. +3  (0..63)
    int ty = tid >> 4;   // edges ty*8 .. +7
    uint64_t acc[8][2];
#pragma unroll
    for (int i = 0; i < 8; i++) { acc[i][0] = 0ull; acc[i][1] = 0ull; }

    const float4* Wp = reinterpret_cast<const float4*>(g_WeT) + tx;
#pragma unroll 8
    for (int k = 0; k < kEDGE; k++) {
        float4 w = __ldg(Wp + k * 16);
        uint64_t w01 = pack2(w.x, w.y), w23 = pack2(w.z, w.w);
        float4 aA = *reinterpret_cast<const float4*>(&sAt[k][ty * 8]);
        float4 aB = *reinterpret_cast<const float4*>(&sAt[k][ty * 8 + 4]);
        { uint64_t aa = pack2(aA.x, aA.x); ffma2(acc[0][0], aa, w01); ffma2(acc[0][1], aa, w23); }
        { uint64_t aa = pack2(aA.y, aA.y); ffma2(acc[1][0], aa, w01); ffma2(acc[1][1], aa, w23); }
        { uint64_t aa = pack2(aA.z, aA.z); ffma2(acc[2][0], aa, w01); ffma2(acc[2][1], aa, w23); }
        { uint64_t aa = pack2(aA.w, aA.w); ffma2(acc[3][0], aa, w01); ffma2(acc[3][1], aa, w23); }
        { uint64_t aa = pack2(aB.x, aB.x); ffma2(acc[4][0], aa, w01); ffma2(acc[4][1], aa, w23); }
        { uint64_t aa = pack2(aB.y, aB.y); ffma2(acc[5][0], aa, w01); ffma2(acc[5][1], aa, w23); }
        { uint64_t aa = pack2(aB.z, aB.z); ffma2(acc[6][0], aa, w01); ffma2(acc[6][1], aa, w23); }
        { uint64_t aa = pack2(aB.w, aB.w); ffma2(acc[7][0], aa, w01); ffma2(acc[7][1], aa, w23); }
    }

    // ---- fused epilogue: gather + leaky-relu + attn dot + per-head reduce ----
    float4 av = __ldg(reinterpret_cast<const float4*>(attn) + tx);  // attn[j..j+3]
    int h = tx >> 2;                 // head of this thread's 4 features
    bool headlead = (tx & 3) == 0;

#pragma unroll
    for (int i = 0; i < 8; i++) {
        int e = e0 + ty * 8 + i;
        int s = __ldg(&src[e]);
        int d = __ldg(&dst[e]);
        float4 fs = *reinterpret_cast<const float4*>(&g_feat_src[s * 64 + tx * 4]);
        float4 fd = *reinterpret_cast<const float4*>(&g_feat_dst[d * 64 + tx * 4]);
        float4 x;
        unpack2(acc[i][0], x.x, x.y);
        unpack2(acc[i][1], x.z, x.w);
        x.x += fs.x + fd.x; x.y += fs.y + fd.y;
        x.z += fs.z + fd.z; x.w += fs.w + fd.w;
        x.x = (x.x > 0.f) ? x.x : NEG_SLOPE * x.x;
        x.y = (x.y > 0.f) ? x.y : NEG_SLOPE * x.y;
        x.z = (x.z > 0.f) ? x.z : NEG_SLOPE * x.z;
        x.w = (x.w > 0.f) ? x.w : NEG_SLOPE * x.w;
        float p = x.x * av.x + x.y * av.y + x.z * av.z + x.w * av.w;
        p += __shfl_xor_sync(0xffffffffu, p, 1);
        p += __shfl_xor_sync(0xffffffffu, p, 2);
        if (headlead) g_logits[e * 4 + h] = p;
        if (tx == 0) atomicAdd(&g_deg[d], 1);
    }
}

// ---------------------------------------------------------------------------
// Scan: deg -> rowptr (exclusive)
// ---------------------------------------------------------------------------
__global__ void scanA_kernel() {
    __shared__ int warpsums[32];
    int i = blockIdx.x * 1024 + threadIdx.x;
    int v = (i < kN) ? g_deg[i] : 0;
    int lane = threadIdx.x & 31, wid = threadIdx.x >> 5;
    int x = v;
#pragma unroll
    for (int o = 1; o < 32; o <<= 1) {
        int t = __shfl_up_sync(0xffffffffu, x, o);
        if (lane >= o) x += t;
    }
    if (lane == 31) warpsums[wid] = x;
    __syncthreads();
    if (wid == 0) {
        int s = warpsums[lane];
#pragma unroll
        for (int o = 1; o < 32; o <<= 1) {
            int t = __shfl_up_sync(0xffffffffu, s, o);
            if (lane >= o) s += t;
        }
        warpsums[lane] = s;
    }
    __syncthreads();
    int base = wid ? warpsums[wid - 1] : 0;
    int incl = base + x;
    if (i < kN) g_rowptr[i] = incl - v;       // exclusive (block-local)
    if (threadIdx.x == 1023) g_partial[blockIdx.x] = incl;
}

__global__ void scanB_kernel() {
    if (threadIdx.x == 0) {
        int s = 0;
        for (int b = 0; b < SCAN_BLOCKS; b++) { int t = g_partial[b]; g_partial[b] = s; s += t; }
    }
}

__global__ void scanC_kernel() {
    int i = blockIdx.x * 1024 + threadIdx.x;
    if (i < kN) g_rowptr[i] += g_partial[blockIdx.x];
    if (blockIdx.x == 0 && threadIdx.x == 0) g_rowptr[kN] = kE;
}

// ---------------------------------------------------------------------------
// K4: scatter edge ids into CSR buckets
// ---------------------------------------------------------------------------
__global__ void scatter_kernel(const int* __restrict__ dst) {
    int e = blockIdx.x * blockDim.x + threadIdx.x;
    int d = dst[e];
    int p = atomicAdd(&g_cursor[d], 1);
    g_edge_list[g_rowptr[d] + p] = e;
}

// ---------------------------------------------------------------------------
// K5: per-dst softmax + weighted aggregation. One warp per node, atomic-free.
// Alpha is computed once (lane-parallel) and written to alpha_out; the
// serial aggregation loop re-reads it (no redundant MUFU), with src-index
// prefetch to hide one L2 latency level.
// ---------------------------------------------------------------------------
__global__ void aggregate_kernel(const int* __restrict__ src,
                                 const float* __restrict__ bias,
                                 float* __restrict__ rst,
                                 float* __restrict__ alpha_out) {
    int n = (blockIdx.x * blockDim.x + threadIdx.x) >> 5;  // grid = exactly N warps
    int lane = threadIdx.x & 31;
    int beg = g_rowptr[n], end = g_rowptr[n + 1];
    const float4* lg4 = reinterpret_cast<const float4*>(g_logits);
    float4* a4 = reinterpret_cast<float4*>(alpha_out);

    // ---- per-head max ----
    float m0 = -3e38f, m1 = -3e38f, m2 = -3e38f, m3 = -3e38f;
    for (int i = beg + lane; i < end; i += 32) {
        float4 l = lg4[g_edge_list[i]];
        m0 = fmaxf(m0, l.x); m1 = fmaxf(m1, l.y);
        m2 = fmaxf(m2, l.z); m3 = fmaxf(m3, l.w);
    }
#pragma unroll
    for (int o = 16; o > 0; o >>= 1) {
        m0 = fmaxf(m0, __shfl_xor_sync(0xffffffffu, m0, o));
        m1 = fmaxf(m1, __shfl_xor_sync(0xffffffffu, m1, o));
        m2 = fmaxf(m2, __shfl_xor_sync(0xffffffffu, m2, o));
        m3 = fmaxf(m3, __shfl_xor_sync(0xffffffffu, m3, o));
    }

    // ---- per-head exp-sum ----
    float s0 = 0.f, s1 = 0.f, s2 = 0.f, s3 = 0.f;
    for (int i = beg + lane; i < end; i += 32) {
        float4 l = lg4[g_edge_list[i]];
        s0 += __expf(l.x - m0); s1 += __expf(l.y - m1);
        s2 += __expf(l.z - m2); s3 += __expf(l.w - m3);
    }
#pragma unroll
    for (int o = 16; o > 0; o >>= 1) {
        s0 += __shfl_xor_sync(0xffffffffu, s0, o);
        s1 += __shfl_xor_sync(0xffffffffu, s1, o);
        s2 += __shfl_xor_sync(0xffffffffu, s2, o);
        s3 += __shfl_xor_sync(0xffffffffu, s3, o);
    }
    float r0 = (s0 > 0.f) ? 1.f / s0 : 0.f;
    float r1 = (s1 > 0.f) ? 1.f / s1 : 0.f;
    float r2 = (s2 > 0.f) ? 1.f / s2 : 0.f;
    float r3 = (s3 > 0.f) ? 1.f / s3 : 0.f;

    // ---- alpha: compute once, lane-parallel over edges ----
    for (int i = beg + lane; i < end; i += 32) {
        int e = g_edge_list[i];
        float4 l = lg4[e];
        a4[e] = make_float4(__expf(l.x - m0) * r0, __expf(l.y - m1) * r1,
                            __expf(l.z - m2) * r2, __expf(l.w - m3) * r3);
    }
    __syncwarp();

    // ---- weighted message aggregation (edge-serial, feature-parallel) ----
    float acc0 = 0.f, acc1 = 0.f;
    bool lo = lane < 16;   // head of feature `lane` is 0/1; of `lane+32` is 2/3
    if (beg < end) {
        int e = g_edge_list[beg];
        int sn = __ldg(&src[e]);
        for (int i = beg; i < end; i++) {
            float4 a = a4[e];
            float f0 = g_feat_src[sn * 64 + lane];
            float f1 = g_feat_src[sn * 64 + 32 + lane];
            int i2 = i + 1;
            int e2 = 0, sn2 = 0;
            if (i2 < end) { e2 = g_edge_list[i2]; sn2 = __ldg(&src[e2]); }
            float al0 = lo ? a.x : a.y;
            float al1 = lo ? a.z : a.w;
            acc0 += al0 * f0;
            acc1 += al1 * f1;
            e = e2; sn = sn2;
        }
    }
    rst[n * 64 + lane]      = acc0 + __ldg(&bias[lane]);
    rst[n * 64 + 32 + lane] = acc1 + __ldg(&bias[32 + lane]);
}

// ---------------------------------------------------------------------------
// K6: copy alpha scratch into the output tail if the harness expects it
// (only launched when alpha lives in g_alpha; when out has room we write
// alpha there directly in aggregate_kernel)
// ---------------------------------------------------------------------------

extern "C" void kernel_launch(void* const* d_in, const int* in_sizes, int n_in,
                              void* d_out, int out_size) {
    (void)in_sizes; (void)n_in;
    const float* node_feat = (const float*)d_in[0];
    const float* edge_feat = (const float*)d_in[1];
    const float* W_src     = (const float*)d_in[2];
    const float* W_dst     = (const float*)d_in[3];
    const float* W_edge    = (const float*)d_in[4];
    const float* attn      = (const float*)d_in[5];
    const float* bias      = (const float*)d_in[6];
    const int*   src       = (const int*)d_in[7];
    const int*   dst       = (const int*)d_in[8];

    float* out = (float*)d_out;
    int write_alpha = (out_size >= kN * kOUT + kE * 4) ? 1 : 0;

    // alpha destination: harness output tail if present, else device scratch
    float* alpha_dest;
    if (write_alpha) {
        alpha_dest = out + (size_t)kN * kOUT;
    } else {
        cudaGetSymbolAddress((void**)&alpha_dest, g_alpha);
    }

    prep_weights_kernel<<<64, 256>>>(W_src, W_dst, W_edge);
    zero_kernel<<<(kN + 255) / 256, 256>>>();
    proj_kernel<<<(kN + 63) / 64, 256>>>(node_feat);
    fused_edge_kernel<<<kE / 128, 256>>>(edge_feat, src, dst, attn);
    scanA_kernel<<<SCAN_BLOCKS, 1024>>>();
    scanB_kernel<<<1, 32>>>();
    scanC_kernel<<<SCAN_BLOCKS, 1024>>>();
    scatter_kernel<<<kE / 256, 256>>>(dst);
    aggregate_kernel<<<kN / 8, 256>>>(src, bias, out, alpha_dest);
}

// round 6
// speedup vs baseline: 1.9882x; 1.4546x over previous
#include <cuda_runtime.h>
#include <cstdint>

// ---------------------------------------------------------------------------
// Problem constants
// ---------------------------------------------------------------------------
#define kN 100000
#define kE 1600000
#define kIN 128
#define kOUT 64
#define kEDGE 32
#define NEG_SLOPE 0.2f
#define SCAN_BLOCKS 98   // ceil(100000/1024)

// ---------------------------------------------------------------------------
// Device scratch (static globals; no runtime allocation)
// ---------------------------------------------------------------------------
__device__ __align__(16) float g_feat_src[kN * kOUT];       // 25.6 MB
__device__ __align__(16) float g_feat_dst[kN * kOUT];       // 25.6 MB
__device__ __align__(16) float g_logits[kE * 4];            // 25.6 MB
__device__ __align__(16) float g_alpha[kE * 4];             // 25.6 MB scratch
__device__ __align__(16) float g_WcT[kIN * kIN];            // [k][j] (j<64: W_src, else W_dst)
__device__ __align__(16) float g_WeT[kEDGE * kOUT];         // [k][j]
__device__ int   g_deg[kN];
__device__ int   g_cursor[kN];
__device__ int   g_rowptr[kN + 1];
__device__ int   g_edge_list[kE];
__device__ int   g_partial[SCAN_BLOCKS];

// ---------------------------------------------------------------------------
// Packed f32x2 FMA helpers (sm_103a FFMA2 — 2x fp32 FMA throughput)
// ---------------------------------------------------------------------------
__device__ __forceinline__ void ffma2(uint64_t& d, uint64_t a, uint64_t b) {
    asm("fma.rn.f32x2 %0, %1, %2, %0;" : "+l"(d) : "l"(a), "l"(b));
}
__device__ __forceinline__ uint64_t pack2(float x, float y) {
    uint64_t r; asm("mov.b64 %0, {%1, %2};" : "=l"(r) : "f"(x), "f"(y)); return r;
}
__device__ __forceinline__ void unpack2(uint64_t v, float& x, float& y) {
    asm("mov.b64 {%0, %1}, %2;" : "=f"(x), "=f"(y) : "l"(v));
}
__device__ __forceinline__ uint32_t smem_u32(const void* p) {
    uint32_t a;
    asm("{ .reg .u64 t; cvta.to.shared.u64 t, %1; cvt.u32.u64 %0, t; }"
        : "=r"(a) : "l"(p));
    return a;
}
__device__ __forceinline__ void cp_async16(uint32_t saddr, const void* gptr) {
    asm volatile("cp.async.cg.shared.global [%0], [%1], 16;" :: "r"(saddr), "l"(gptr));
}

// ---------------------------------------------------------------------------
// K0: transpose weights once (tiny)
// ---------------------------------------------------------------------------
__global__ void prep_weights_kernel(const float* __restrict__ Ws,
                                    const float* __restrict__ Wd,
                                    const float* __restrict__ We) {
    int stride = gridDim.x * blockDim.x;
    int t0 = blockIdx.x * blockDim.x + threadIdx.x;
    for (int i = t0; i < kIN * kIN; i += stride) {
        int k = i >> 7, j = i & 127;
        g_WcT[i] = (j < 64) ? Ws[j * kIN + k] : Wd[(j - 64) * kIN + k];
    }
    for (int i = t0; i < kEDGE * kOUT; i += stride) {
        int k = i >> 6, j = i & 63;
        g_WeT[i] = We[j * kEDGE + k];
    }
}

__global__ void zero_kernel() {
    int i = blockIdx.x * blockDim.x + threadIdx.x;
    if (i < kN) { g_deg[i] = 0; g_cursor[i] = 0; }
}

// ---------------------------------------------------------------------------
// K1: node projections  feat_src/feat_dst[N,64] = node_feat @ {W_src,W_dst}^T
// ---------------------------------------------------------------------------
__global__ void proj_kernel(const float* __restrict__ node_feat) {
    __shared__ __align__(16) float sAt[kIN][68];
    int tid = threadIdx.x;
    int n0 = blockIdx.x * 64;

#pragma unroll
    for (int r = 0; r < 32; r++) {
        int idx = r * 256 + tid;          // 0..8191
        int node = idx >> 7;
        int k = idx & 127;
        int gn = n0 + node;
        float v = (gn < kN) ? node_feat[gn * kIN + k] : 0.f;
        sAt[k][node] = v;
    }
    __syncthreads();

    int tx = tid & 31;   // outs j = tx*4 .. tx*4+3   (0..127)
    int ty = tid >> 5;   // nodes ty*8 .. ty*8+7
    uint64_t acc[8][2];
#pragma unroll
    for (int i = 0; i < 8; i++) { acc[i][0] = 0ull; acc[i][1] = 0ull; }

    const float4* Wp = reinterpret_cast<const float4*>(g_WcT) + tx;
#pragma unroll 8
    for (int k = 0; k < kIN; k++) {
        float4 w = __ldg(Wp + k * 32);
        uint64_t w01 = pack2(w.x, w.y), w23 = pack2(w.z, w.w);
        float4 aA = *reinterpret_cast<const float4*>(&sAt[k][ty * 8]);
        float4 aB = *reinterpret_cast<const float4*>(&sAt[k][ty * 8 + 4]);
        { uint64_t aa = pack2(aA.x, aA.x); ffma2(acc[0][0], aa, w01); ffma2(acc[0][1], aa, w23); }
        { uint64_t aa = pack2(aA.y, aA.y); ffma2(acc[1][0], aa, w01); ffma2(acc[1][1], aa, w23); }
        { uint64_t aa = pack2(aA.z, aA.z); ffma2(acc[2][0], aa, w01); ffma2(acc[2][1], aa, w23); }
        { uint64_t aa = pack2(aA.w, aA.w); ffma2(acc[3][0], aa, w01); ffma2(acc[3][1], aa, w23); }
        { uint64_t aa = pack2(aB.x, aB.x); ffma2(acc[4][0], aa, w01); ffma2(acc[4][1], aa, w23); }
        { uint64_t aa = pack2(aB.y, aB.y); ffma2(acc[5][0], aa, w01); ffma2(acc[5][1], aa, w23); }
        { uint64_t aa = pack2(aB.z, aB.z); ffma2(acc[6][0], aa, w01); ffma2(acc[6][1], aa, w23); }
        { uint64_t aa = pack2(aB.w, aB.w); ffma2(acc[7][0], aa, w01); ffma2(acc[7][1], aa, w23); }
    }

    int j = tx * 4;
#pragma unroll
    for (int i = 0; i < 8; i++) {
        int gn = n0 + ty * 8 + i;
        if (gn >= kN) continue;
        float4 o;
        unpack2(acc[i][0], o.x, o.y);
        unpack2(acc[i][1], o.z, o.w);
        if (j < 64) *reinterpret_cast<float4*>(&g_feat_src[gn * 64 + j]) = o;
        else        *reinterpret_cast<float4*>(&g_feat_dst[gn * 64 + (j - 64)]) = o;
    }
}

// ---------------------------------------------------------------------------
// K2: FUSED edge GEMM + logits + degree histogram, with cp.async prefetch.
// Tile: 64 edges x 64 outs per block, 128 threads (tx=outs/4, ty=edges/8).
// fs/fd rows are prefetched into smem via LDGSTS *before* the GEMM mainloop,
// so their L2 latency is hidden by ~1000 cycles of FFMA2 issue. Epilogue
// then runs entirely out of shared memory.
// ---------------------------------------------------------------------------
#define FE_EDGES 64
__global__ __launch_bounds__(128) void fused_edge_kernel(
        const float* __restrict__ edge_feat,
        const int* __restrict__ src,
        const int* __restrict__ dst,
        const float* __restrict__ attn) {
    __shared__ __align__(16) float sAt[kEDGE][FE_EDGES + 4];   // edge_feat^T tile
    __shared__ __align__(16) float sFs[FE_EDGES][kOUT];        // gathered feat_src rows
    __shared__ __align__(16) float sFd[FE_EDGES][kOUT];        // gathered feat_dst rows
    __shared__ int sSrc[FE_EDGES];
    __shared__ int sDst[FE_EDGES];

    int tid = threadIdx.x;
    int e0 = blockIdx.x * FE_EDGES;

    // ---- stage indices (+ degree histogram) ----
    if (tid < FE_EDGES) {
        sSrc[tid] = __ldg(&src[e0 + tid]);
    } else {
        int d = __ldg(&dst[e0 + tid - FE_EDGES]);
        sDst[tid - FE_EDGES] = d;
        atomicAdd(&g_deg[d], 1);
    }
    __syncthreads();

    // ---- issue async gathers of fs/fd rows (2048 x 16B; 16 per thread) ----
#pragma unroll
    for (int j = 0; j < 16; j++) {
        int idx = j * 128 + tid;        // 0..2047
        int c     = idx & 15;           // 16B chunk within 256B row
        int which = (idx >> 4) & 1;     // 0 = fs, 1 = fd
        int el    = idx >> 5;           // edge-local 0..63
        const float* gp;
        uint32_t sa;
        if (which == 0) {
            gp = &g_feat_src[(size_t)sSrc[el] * kOUT + c * 4];
            sa = smem_u32(&sFs[el][c * 4]);
        } else {
            gp = &g_feat_dst[(size_t)sDst[el] * kOUT + c * 4];
            sa = smem_u32(&sFd[el][c * 4]);
        }
        cp_async16(sa, gp);
    }
    asm volatile("cp.async.commit_group;");

    // ---- load edge_feat tile (transposed) ----
#pragma unroll
    for (int j = 0; j < 4; j++) {
        int idx = j * 128 + tid;        // 0..511
        int el = idx >> 3;              // edge-local
        int c  = idx & 7;               // float4 chunk within 32-float row
        float4 v = __ldg(reinterpret_cast<const float4*>(
                         &edge_feat[(size_t)(e0 + el) * kEDGE + c * 4]));
        sAt[c * 4 + 0][el] = v.x;
        sAt[c * 4 + 1][el] = v.y;
        sAt[c * 4 + 2][el] = v.z;
        sAt[c * 4 + 3][el] = v.w;
    }
    __syncthreads();

    // ---- GEMM mainloop: acc[8 edges][4 outs] ----
    int tx = tid & 15;   // outs j = tx*4 .. +3  (0..63)
    int ty = tid >> 4;   // edges ty*8 .. +7
    uint64_t acc[8][2];
#pragma unroll
    for (int i = 0; i < 8; i++) { acc[i][0] = 0ull; acc[i][1] = 0ull; }

    const float4* Wp = reinterpret_cast<const float4*>(g_WeT) + tx;
#pragma unroll 8
    for (int k = 0; k < kEDGE; k++) {
        float4 w = __ldg(Wp + k * 16);
        uint64_t w01 = pack2(w.x, w.y), w23 = pack2(w.z, w.w);
        float4 aA = *reinterpret_cast<const float4*>(&sAt[k][ty * 8]);
        float4 aB = *reinterpret_cast<const float4*>(&sAt[k][ty * 8 + 4]);
        { uint64_t aa = pack2(aA.x, aA.x); ffma2(acc[0][0], aa, w01); ffma2(acc[0][1], aa, w23); }
        { uint64_t aa = pack2(aA.y, aA.y); ffma2(acc[1][0], aa, w01); ffma2(acc[1][1], aa, w23); }
        { uint64_t aa = pack2(aA.z, aA.z); ffma2(acc[2][0], aa, w01); ffma2(acc[2][1], aa, w23); }
        { uint64_t aa = pack2(aA.w, aA.w); ffma2(acc[3][0], aa, w01); ffma2(acc[3][1], aa, w23); }
        { uint64_t aa = pack2(aB.x, aB.x); ffma2(acc[4][0], aa, w01); ffma2(acc[4][1], aa, w23); }
        { uint64_t aa = pack2(aB.y, aB.y); ffma2(acc[5][0], aa, w01); ffma2(acc[5][1], aa, w23); }
        { uint64_t aa = pack2(aB.z, aB.z); ffma2(acc[6][0], aa, w01); ffma2(acc[6][1], aa, w23); }
        { uint64_t aa = pack2(aB.w, aB.w); ffma2(acc[7][0], aa, w01); ffma2(acc[7][1], aa, w23); }
    }

    // ---- wait for gathers (long since landed), then epilogue from smem ----
    asm volatile("cp.async.wait_group 0;");
    __syncthreads();

    float4 av = __ldg(reinterpret_cast<const float4*>(attn) + tx);  // attn[j..j+3]
    int h = tx >> 2;
    bool headlead = (tx & 3) == 0;

#pragma unroll
    for (int i = 0; i < 8; i++) {
        int el = ty * 8 + i;
        int e = e0 + el;
        float4 fs = *reinterpret_cast<const float4*>(&sFs[el][tx * 4]);
        float4 fd = *reinterpret_cast<const float4*>(&sFd[el][tx * 4]);
        float4 x;
        unpack2(acc[i][0], x.x, x.y);
        unpack2(acc[i][1], x.z, x.w);
        x.x += fs.x + fd.x; x.y += fs.y + fd.y;
        x.z += fs.z + fd.z; x.w += fs.w + fd.w;
        x.x = (x.x > 0.f) ? x.x : NEG_SLOPE * x.x;
        x.y = (x.y > 0.f) ? x.y : NEG_SLOPE * x.y;
        x.z = (x.z > 0.f) ? x.z : NEG_SLOPE * x.z;
        x.w = (x.w > 0.f) ? x.w : NEG_SLOPE * x.w;
        float p = x.x * av.x + x.y * av.y + x.z * av.z + x.w * av.w;
        p += __shfl_xor_sync(0xffffffffu, p, 1);
        p += __shfl_xor_sync(0xffffffffu, p, 2);
        if (headlead) g_logits[e * 4 + h] = p;
    }
}

// ---------------------------------------------------------------------------
// Scan: deg -> rowptr (exclusive)
// ---------------------------------------------------------------------------
__global__ void scanA_kernel() {
    __shared__ int warpsums[32];
    int i = blockIdx.x * 1024 + threadIdx.x;
    int v = (i < kN) ? g_deg[i] : 0;
    int lane = threadIdx.x & 31, wid = threadIdx.x >> 5;
    int x = v;
#pragma unroll
    for (int o = 1; o < 32; o <<= 1) {
        int t = __shfl_up_sync(0xffffffffu, x, o);
        if (lane >= o) x += t;
    }
    if (lane == 31) warpsums[wid] = x;
    __syncthreads();
    if (wid == 0) {
        int s = warpsums[lane];
#pragma unroll
        for (int o = 1; o < 32; o <<= 1) {
            int t = __shfl_up_sync(0xffffffffu, s, o);
            if (lane >= o) s += t;
        }
        warpsums[lane] = s;
    }
    __syncthreads();
    int base = wid ? warpsums[wid - 1] : 0;
    int incl = base + x;
    if (i < kN) g_rowptr[i] = incl - v;       // exclusive (block-local)
    if (threadIdx.x == 1023) g_partial[blockIdx.x] = incl;
}

__global__ void scanB_kernel() {
    if (threadIdx.x == 0) {
        int s = 0;
        for (int b = 0; b < SCAN_BLOCKS; b++) { int t = g_partial[b]; g_partial[b] = s; s += t; }
    }
}

__global__ void scanC_kernel() {
    int i = blockIdx.x * 1024 + threadIdx.x;
    if (i < kN) g_rowptr[i] += g_partial[blockIdx.x];
    if (blockIdx.x == 0 && threadIdx.x == 0) g_rowptr[kN] = kE;
}

// ---------------------------------------------------------------------------
// K4: scatter edge ids into CSR buckets
// ---------------------------------------------------------------------------
__global__ void scatter_kernel(const int* __restrict__ dst) {
    int e = blockIdx.x * blockDim.x + threadIdx.x;
    int d = dst[e];
    int p = atomicAdd(&g_cursor[d], 1);
    g_edge_list[g_rowptr[d] + p] = e;
}

// ---------------------------------------------------------------------------
// K5: per-dst softmax + weighted aggregation. One warp per node, atomic-free.
// ---------------------------------------------------------------------------
__global__ void aggregate_kernel(const int* __restrict__ src,
                                 const float* __restrict__ bias,
                                 float* __restrict__ rst,
                                 float* __restrict__ alpha_out) {
    int n = (blockIdx.x * blockDim.x + threadIdx.x) >> 5;  // grid = exactly N warps
    int lane = threadIdx.x & 31;
    int beg = g_rowptr[n], end = g_rowptr[n + 1];
    const float4* lg4 = reinterpret_cast<const float4*>(g_logits);
    float4* a4 = reinterpret_cast<float4*>(alpha_out);

    // ---- per-head max ----
    float m0 = -3e38f, m1 = -3e38f, m2 = -3e38f, m3 = -3e38f;
    for (int i = beg + lane; i < end; i += 32) {
        float4 l = lg4[g_edge_list[i]];
        m0 = fmaxf(m0, l.x); m1 = fmaxf(m1, l.y);
        m2 = fmaxf(m2, l.z); m3 = fmaxf(m3, l.w);
    }
#pragma unroll
    for (int o = 16; o > 0; o >>= 1) {
        m0 = fmaxf(m0, __shfl_xor_sync(0xffffffffu, m0, o));
        m1 = fmaxf(m1, __shfl_xor_sync(0xffffffffu, m1, o));
        m2 = fmaxf(m2, __shfl_xor_sync(0xffffffffu, m2, o));
        m3 = fmaxf(m3, __shfl_xor_sync(0xffffffffu, m3, o));
    }

    // ---- per-head exp-sum ----
    float s0 = 0.f, s1 = 0.f, s2 = 0.f, s3 = 0.f;
    for (int i = beg + lane; i < end; i += 32) {
        float4 l = lg4[g_edge_list[i]];
        s0 += __expf(l.x - m0); s1 += __expf(l.y - m1);
        s2 += __expf(l.z - m2); s3 += __expf(l.w - m3);
    }
#pragma unroll
    for (int o = 16; o > 0; o >>= 1) {
        s0 += __shfl_xor_sync(0xffffffffu, s0, o);
        s1 += __shfl_xor_sync(0xffffffffu, s1, o);
        s2 += __shfl_xor_sync(0xffffffffu, s2, o);
        s3 += __shfl_xor_sync(0xffffffffu, s3, o);
    }
    float r0 = (s0 > 0.f) ? 1.f / s0 : 0.f;
    float r1 = (s1 > 0.f) ? 1.f / s1 : 0.f;
    float r2 = (s2 > 0.f) ? 1.f / s2 : 0.f;
    float r3 = (s3 > 0.f) ? 1.f / s3 : 0.f;

    // ---- alpha: compute once, lane-parallel over edges ----
    for (int i = beg + lane; i < end; i += 32) {
        int e = g_edge_list[i];
        float4 l = lg4[e];
        a4[e] = make_float4(__expf(l.x - m0) * r0, __expf(l.y - m1) * r1,
                            __expf(l.z - m2) * r2, __expf(l.w - m3) * r3);
    }
    __syncwarp();

    // ---- weighted message aggregation (edge-serial, feature-parallel) ----
    float acc0 = 0.f, acc1 = 0.f;
    bool lo = lane < 16;   // head of feature `lane` is 0/1; of `lane+32` is 2/3
    if (beg < end) {
        int e = g_edge_list[beg];
        int sn = __ldg(&src[e]);
        for (int i = beg; i < end; i++) {
            float4 a = a4[e];
            float f0 = g_feat_src[sn * 64 + lane];
            float f1 = g_feat_src[sn * 64 + 32 + lane];
            int i2 = i + 1;
            int e2 = 0, sn2 = 0;
            if (i2 < end) { e2 = g_edge_list[i2]; sn2 = __ldg(&src[e2]); }
            float al0 = lo ? a.x : a.y;
            float al1 = lo ? a.z : a.w;
            acc0 += al0 * f0;
            acc1 += al1 * f1;
            e = e2; sn = sn2;
        }
    }
    rst[n * 64 + lane]      = acc0 + __ldg(&bias[lane]);
    rst[n * 64 + 32 + lane] = acc1 + __ldg(&bias[32 + lane]);
}

// ---------------------------------------------------------------------------
// Launcher
// ---------------------------------------------------------------------------
extern "C" void kernel_launch(void* const* d_in, const int* in_sizes, int n_in,
                              void* d_out, int out_size) {
    (void)in_sizes; (void)n_in;
    const float* node_feat = (const float*)d_in[0];
    const float* edge_feat = (const float*)d_in[1];
    const float* W_src     = (const float*)d_in[2];
    const float* W_dst     = (const float*)d_in[3];
    const float* W_edge    = (const float*)d_in[4];
    const float* attn      = (const float*)d_in[5];
    const float* bias      = (const float*)d_in[6];
    const int*   src       = (const int*)d_in[7];
    const int*   dst       = (const int*)d_in[8];

    float* out = (float*)d_out;
    int write_alpha = (out_size >= kN * kOUT + kE * 4) ? 1 : 0;

    float* alpha_dest;
    if (write_alpha) {
        alpha_dest = out + (size_t)kN * kOUT;
    } else {
        cudaGetSymbolAddress((void**)&alpha_dest, g_alpha);
    }

    prep_weights_kernel<<<64, 256>>>(W_src, W_dst, W_edge);
    zero_kernel<<<(kN + 255) / 256, 256>>>();
    proj_kernel<<<(kN + 63) / 64, 256>>>(node_feat);
    fused_edge_kernel<<<kE / FE_EDGES, 128>>>(edge_feat, src, dst, attn);
    scanA_kernel<<<SCAN_BLOCKS, 1024>>>();
    scanB_kernel<<<1, 32>>>();
    scanC_kernel<<<SCAN_BLOCKS, 1024>>>();
    scatter_kernel<<<kE / 256, 256>>>(dst);
    aggregate_kernel<<<kN / 8, 256>>>(src, bias, out, alpha_dest);
}